// round 1
// baseline (speedup 1.0000x reference)
#include <cuda_runtime.h>
#include <math.h>

// Problem constants
#define BB 16
#define CC 32
#define TT 512
#define SS 128       // GAF_SIZE
#define NIMG (BB*CC) // 512
#define LATENT 128

// ---------------- scratch (no allocation allowed) ----------------
__device__ float g_gaf[(size_t)NIMG * 2 * SS * SS];        // 512*2*128*128  = 16.8M f
__device__ float g_h1 [(size_t)NIMG * 32 * 64 * 64];       // 67.1M f
__device__ float g_h2 [(size_t)NIMG * 64 * 32 * 32];       // 33.6M f
__device__ float g_h3 [(size_t)NIMG * 128 * 16 * 16];      // 16.8M f
__device__ float g_h4 [(size_t)NIMG * 256 * 8 * 8];        // 8.4M f
__device__ float g_pbar[BB * 256];

// ---------------- GAF kernel: one block per (b,c) image ----------------
__global__ void gaf_kernel(const float* __restrict__ x_raw)
{
    const int img = blockIdx.x;      // b*32+c
    const int tid = threadIdx.x;     // 0..127
    __shared__ float xs[SS];
    __shared__ float ssq[SS];
    __shared__ float smn[4], smx[4];

    // mean over T/S = 4 consecutive samples
    const float4 v4 = *(const float4*)(x_raw + (size_t)img * TT + tid * 4);
    float v = 0.25f * (v4.x + v4.y + v4.z + v4.w);

    // block min/max
    float mn = v, mx = v;
    #pragma unroll
    for (int o = 16; o > 0; o >>= 1) {
        mn = fminf(mn, __shfl_xor_sync(0xffffffffu, mn, o));
        mx = fmaxf(mx, __shfl_xor_sync(0xffffffffu, mx, o));
    }
    const int warp = tid >> 5, lane = tid & 31;
    if (lane == 0) { smn[warp] = mn; smx[warp] = mx; }
    __syncthreads();
    mn = fminf(fminf(smn[0], smn[1]), fminf(smn[2], smn[3]));
    mx = fmaxf(fmaxf(smx[0], smx[1]), fmaxf(smx[2], smx[3]));

    float xn = 2.0f * (v - mn) / (mx - mn + 1e-8f) - 1.0f;
    xn = fminf(1.0f, fmaxf(-1.0f, xn));
    float sq = sqrtf(fminf(1.0f, fmaxf(0.0f, 1.0f - xn * xn)));
    xs[tid] = xn;
    ssq[tid] = sq;
    __syncthreads();

    const float xi = xs[tid], si = ssq[tid];
    float* __restrict__ g0 = g_gaf + (size_t)img * (2 * SS * SS) + tid * SS;        // GASF row
    float* __restrict__ g1 = g0 + SS * SS;                                          // GADF row
    #pragma unroll 4
    for (int j = 0; j < SS; j++) {
        const float xj = xs[j], sj = ssq[j];
        g0[j] = xi * xj - si * sj;
        g1[j] = si * xj - xi * sj;
    }
}

// ---------------- Direct conv, 3x3 stride 2, SAME (pad lo=0, hi=1), +bias +ReLU ----------
// Each thread: 4 consecutive ow outputs x 4 consecutive couts.
// block = NSTRIP * CSUB threads. grid = (N, COUT/(4*CSUB), STRIPS/NSTRIP)
template<int CIN, int HIN, int COUT, int NSTRIP, int CSUB>
__global__ void __launch_bounds__(NSTRIP * CSUB)
conv2d_s2(const float* __restrict__ in, const float* __restrict__ W,
          const float* __restrict__ bias, float* __restrict__ out)
{
    constexpr int HOUT = HIN / 2;
    constexpr int WQ = HOUT / 4;             // 4-wide strips per output row
    const int tid  = threadIdx.x;
    const int sid  = (tid % NSTRIP) + blockIdx.z * NSTRIP;  // strip id
    const int csub = tid / NSTRIP;
    const int n    = blockIdx.x;
    const int cout0 = (blockIdx.y * CSUB + csub) * 4;
    const int oh  = sid / WQ;
    const int ow0 = (sid % WQ) * 4;

    const float* __restrict__ inN = in + (size_t)n * CIN * HIN * HIN;

    float acc[4][4];
    #pragma unroll
    for (int c = 0; c < 4; c++)
        #pragma unroll
        for (int o = 0; o < 4; o++) acc[c][o] = 0.0f;

    for (int ci = 0; ci < CIN; ci++) {
        // weights for 4 couts, this cin (warp-uniform -> broadcast loads)
        float w[4][9];
        #pragma unroll
        for (int c = 0; c < 4; c++) {
            const float* wp = W + ((size_t)(cout0 + c) * CIN + ci) * 9;
            #pragma unroll
            for (int t = 0; t < 9; t++) w[c][t] = __ldg(wp + t);
        }
        const float* __restrict__ inC = inN + (size_t)ci * HIN * HIN;
        #pragma unroll
        for (int kh = 0; kh < 3; kh++) {
            const int ih = oh * 2 + kh;
            if (ih >= HIN) break;   // bottom SAME padding (zero)
            const float* row = inC + (size_t)ih * HIN + ow0 * 2;
            float r[9];
            const float4 a = *(const float4*)row;
            const float4 b = *(const float4*)(row + 4);
            r[0]=a.x; r[1]=a.y; r[2]=a.z; r[3]=a.w;
            r[4]=b.x; r[5]=b.y; r[6]=b.z; r[7]=b.w;
            r[8] = (ow0 * 2 + 8 < HIN) ? row[8] : 0.0f;   // right SAME padding
            #pragma unroll
            for (int c = 0; c < 4; c++)
                #pragma unroll
                for (int o = 0; o < 4; o++) {
                    acc[c][o] = fmaf(w[c][kh*3+0], r[2*o+0], acc[c][o]);
                    acc[c][o] = fmaf(w[c][kh*3+1], r[2*o+1], acc[c][o]);
                    acc[c][o] = fmaf(w[c][kh*3+2], r[2*o+2], acc[c][o]);
                }
        }
    }

    #pragma unroll
    for (int c = 0; c < 4; c++) {
        const float bv = __ldg(bias + cout0 + c);
        float4 v;
        v.x = fmaxf(acc[c][0] + bv, 0.0f);
        v.y = fmaxf(acc[c][1] + bv, 0.0f);
        v.z = fmaxf(acc[c][2] + bv, 0.0f);
        v.w = fmaxf(acc[c][3] + bv, 0.0f);
        float* op = out + (((size_t)n * COUT + cout0 + c) * HOUT + oh) * HOUT + ow0;
        *(float4*)op = v;
    }
}

// ---------------- pool over 8x8 spatial AND over C=32 heads -> pbar[16][256] ----------
__global__ void pool_kernel()
{
    // grid = 16*256 blocks, 64 threads: sum over c in [0,32), p in [0,64)
    const int b = blockIdx.x >> 8;
    const int k = blockIdx.x & 255;
    const int p = threadIdx.x;
    float s = 0.0f;
    #pragma unroll
    for (int c = 0; c < CC; c++)
        s += g_h4[(((size_t)(b * CC + c)) * 256 + k) * 64 + p];
    // reduce 64 -> 1
    #pragma unroll
    for (int o = 16; o > 0; o >>= 1)
        s += __shfl_xor_sync(0xffffffffu, s, o);
    __shared__ float sh[2];
    if ((p & 31) == 0) sh[p >> 5] = s;
    __syncthreads();
    if (p == 0) g_pbar[b * 256 + k] = (sh[0] + sh[1]) * (1.0f / (CC * 64));
}

// ---------------- FC: out[b][l] = pbar[b] . Wfc[:,l] + bfc[l] ----------
__global__ void fc_kernel(const float* __restrict__ Wfc, const float* __restrict__ bfc,
                          float* __restrict__ out)
{
    const int b = blockIdx.x;
    const int l = threadIdx.x;
    float s = bfc[l];
    const float* p = g_pbar + b * 256;
    #pragma unroll 8
    for (int k = 0; k < 256; k++)
        s = fmaf(p[k], Wfc[k * LATENT + l], s);
    out[b * LATENT + l] = s;
}

// ---------------- launch ----------------
extern "C" void kernel_launch(void* const* d_in, const int* in_sizes, int n_in,
                              void* d_out, int out_size)
{
    const float* x_raw = (const float*)d_in[0];
    const float* W1 = (const float*)d_in[1];  const float* b1 = (const float*)d_in[2];
    const float* W2 = (const float*)d_in[3];  const float* b2 = (const float*)d_in[4];
    const float* W3 = (const float*)d_in[5];  const float* b3 = (const float*)d_in[6];
    const float* W4 = (const float*)d_in[7];  const float* b4 = (const float*)d_in[8];
    const float* Wfc = (const float*)d_in[9]; const float* bfc = (const float*)d_in[10];
    float* out = (float*)d_out;

    float *gaf, *h1, *h2, *h3, *h4;
    cudaGetSymbolAddress((void**)&gaf, g_gaf);
    cudaGetSymbolAddress((void**)&h1, g_h1);
    cudaGetSymbolAddress((void**)&h2, g_h2);
    cudaGetSymbolAddress((void**)&h3, g_h3);
    cudaGetSymbolAddress((void**)&h4, g_h4);

    gaf_kernel<<<NIMG, 128>>>(x_raw);

    // L1: 2 -> 32, 128 -> 64.   strips = 64*16 = 1024
    conv2d_s2<2, 128, 32, 128, 1><<<dim3(NIMG, 32 / 4, 1024 / 128), 128>>>(gaf, W1, b1, h1);
    // L2: 32 -> 64, 64 -> 32.   strips = 32*8 = 256
    conv2d_s2<32, 64, 64, 128, 1><<<dim3(NIMG, 64 / 4, 256 / 128), 128>>>(h1, W2, b2, h2);
    // L3: 64 -> 128, 32 -> 16.  strips = 16*4 = 64
    conv2d_s2<64, 32, 128, 64, 2><<<dim3(NIMG, 128 / 8, 1), 128>>>(h2, W3, b3, h3);
    // L4: 128 -> 256, 16 -> 8.  strips = 8*2 = 16
    conv2d_s2<128, 16, 256, 16, 8><<<dim3(NIMG, 256 / 32, 1), 128>>>(h3, W4, b4, h4);

    pool_kernel<<<BB * 256, 64>>>();
    fc_kernel<<<BB, LATENT>>>(Wfc, bfc, out);
}

// round 3
// speedup vs baseline: 1.2907x; 1.2907x over previous
#include <cuda_runtime.h>
#include <math.h>

// Problem constants
#define BB 16
#define CC 32
#define TT 512
#define SS 128       // GAF_SIZE
#define NIMG (BB*CC) // 512
#define LATENT 128

// ---------------- scratch (no allocation allowed) ----------------
__device__ float g_gaf[(size_t)NIMG * 2 * SS * SS];
__device__ float g_h1 [(size_t)NIMG * 32 * 64 * 64];
__device__ float g_h2 [(size_t)NIMG * 64 * 32 * 32];
__device__ float g_h3 [(size_t)NIMG * 128 * 16 * 16];
__device__ float g_h4 [(size_t)NIMG * 256 * 8 * 8];
__device__ float g_pbar[BB * 256];
// repacked weights: W'[ci][t][cout], t = kh*3+kw
__device__ float g_wr1[2   * 9 * 32];
__device__ float g_wr2[32  * 9 * 64];
__device__ float g_wr3[64  * 9 * 128];
__device__ float g_wr4[128 * 9 * 256];

// ---------------- f32x2 helpers ----------------
__device__ __forceinline__ unsigned long long pk2(float a, float b) {
    unsigned long long r;
    asm("mov.b64 %0, {%1, %2};" : "=l"(r) : "f"(a), "f"(b));
    return r;
}
__device__ __forceinline__ void upk2(unsigned long long v, float& a, float& b) {
    asm("mov.b64 {%0, %1}, %2;" : "=f"(a), "=f"(b) : "l"(v));
}
__device__ __forceinline__ void fma2(unsigned long long& d, unsigned long long a, unsigned long long b) {
    asm("fma.rn.f32x2 %0, %1, %2, %3;" : "=l"(d) : "l"(a), "l"(b), "l"(d));
}

// ---------------- GAF kernel ----------------
__global__ void gaf_kernel(const float* __restrict__ x_raw)
{
    const int img = blockIdx.x;
    const int tid = threadIdx.x;   // 0..127
    __shared__ float xs[SS];
    __shared__ float ssq[SS];
    __shared__ float smn[4], smx[4];

    const float4 v4 = *(const float4*)(x_raw + (size_t)img * TT + tid * 4);
    float v = 0.25f * (v4.x + v4.y + v4.z + v4.w);

    float mn = v, mx = v;
    #pragma unroll
    for (int o = 16; o > 0; o >>= 1) {
        mn = fminf(mn, __shfl_xor_sync(0xffffffffu, mn, o));
        mx = fmaxf(mx, __shfl_xor_sync(0xffffffffu, mx, o));
    }
    const int warp = tid >> 5, lane = tid & 31;
    if (lane == 0) { smn[warp] = mn; smx[warp] = mx; }
    __syncthreads();
    mn = fminf(fminf(smn[0], smn[1]), fminf(smn[2], smn[3]));
    mx = fmaxf(fmaxf(smx[0], smx[1]), fmaxf(smx[2], smx[3]));

    float xn = 2.0f * (v - mn) / (mx - mn + 1e-8f) - 1.0f;
    xn = fminf(1.0f, fmaxf(-1.0f, xn));
    float sq = sqrtf(fminf(1.0f, fmaxf(0.0f, 1.0f - xn * xn)));
    xs[tid] = xn;
    ssq[tid] = sq;
    __syncthreads();

    const float xi = xs[tid], si = ssq[tid];
    float* __restrict__ g0 = g_gaf + (size_t)img * (2 * SS * SS) + tid * SS;
    float* __restrict__ g1 = g0 + SS * SS;
    #pragma unroll 4
    for (int j = 0; j < SS; j++) {
        const float xj = xs[j], sj = ssq[j];
        g0[j] = xi * xj - si * sj;
        g1[j] = si * xj - xi * sj;
    }
}

// ---------------- weight repack: W[cout][cin][3][3] -> W'[cin][t][cout] ----------------
__global__ void repack_kernel(const float* __restrict__ W, float* __restrict__ Wr,
                              int CIN, int COUT)
{
    int idx = blockIdx.x * blockDim.x + threadIdx.x;
    int total = CIN * COUT * 9;
    if (idx >= total) return;
    int co = idx % COUT;
    int t  = (idx / COUT) % 9;
    int ci = idx / (COUT * 9);
    Wr[idx] = W[((size_t)co * CIN + ci) * 9 + t];
}

// ---------------- Direct conv 3x3 s2 SAME + bias + ReLU, FFMA2 over cout pairs --------
// Thread: 4 consecutive ow x 8 consecutive couts (4 f32x2 cout-pairs).
template<int CIN, int HIN, int COUT, int NSTRIP, int CSUB>
__global__ void __launch_bounds__(NSTRIP * CSUB)
conv2d_s2(const float* __restrict__ in, const float* __restrict__ Wr,
          const float* __restrict__ bias, float* __restrict__ out)
{
    constexpr int HOUT = HIN / 2;
    constexpr int WQ = HOUT / 4;
    const int tid   = threadIdx.x;
    const int sid   = (tid % NSTRIP) + blockIdx.z * NSTRIP;
    const int csub  = tid / NSTRIP;
    const int n     = blockIdx.x;
    const int cout0 = (blockIdx.y * CSUB + csub) * 8;
    const int oh  = sid / WQ;
    const int ow0 = (sid % WQ) * 4;

    const float* __restrict__ inN = in + (size_t)n * CIN * HIN * HIN;

    unsigned long long acc[4][4];   // [cout-pair][ow]
    #pragma unroll
    for (int cp = 0; cp < 4; cp++)
        #pragma unroll
        for (int o = 0; o < 4; o++) acc[cp][o] = 0ull;

    const bool rguard = (ow0 * 2 + 8 < HIN);

    for (int ci = 0; ci < CIN; ci++) {
        const float* __restrict__ wbase = Wr + ((size_t)ci * 9) * COUT + cout0;
        const float* __restrict__ inC = inN + (size_t)ci * HIN * HIN;
        #pragma unroll
        for (int kh = 0; kh < 3; kh++) {
            const int ih = oh * 2 + kh;
            if (ih >= HIN) break;             // bottom SAME pad (zero)
            const float* row = inC + (size_t)ih * HIN + ow0 * 2;
            float r[9];
            const float4 a = *(const float4*)row;
            const float4 b = *(const float4*)(row + 4);
            r[0]=a.x; r[1]=a.y; r[2]=a.z; r[3]=a.w;
            r[4]=b.x; r[5]=b.y; r[6]=b.z; r[7]=b.w;
            r[8] = rguard ? row[8] : 0.0f;    // right SAME pad
            unsigned long long pb[9];
            #pragma unroll
            for (int v = 0; v < 9; v++) pb[v] = pk2(r[v], r[v]);

            #pragma unroll
            for (int kw = 0; kw < 3; kw++) {
                const float* wp = wbase + (kh * 3 + kw) * COUT;
                const ulonglong2 wa = *(const ulonglong2*)(wp);      // couts 0..3 as 2 pairs
                const ulonglong2 wb = *(const ulonglong2*)(wp + 4);  // couts 4..7
                #pragma unroll
                for (int o = 0; o < 4; o++) {
                    const unsigned long long x = pb[2 * o + kw];
                    fma2(acc[0][o], wa.x, x);
                    fma2(acc[1][o], wa.y, x);
                    fma2(acc[2][o], wb.x, x);
                    fma2(acc[3][o], wb.y, x);
                }
            }
        }
    }

    #pragma unroll
    for (int cp = 0; cp < 4; cp++) {
        const int c0 = cout0 + 2 * cp;
        const float bv0 = __ldg(bias + c0);
        const float bv1 = __ldg(bias + c0 + 1);
        float4 v0, v1;
        float lo, hi;
        upk2(acc[cp][0], lo, hi); v0.x = fmaxf(lo + bv0, 0.f); v1.x = fmaxf(hi + bv1, 0.f);
        upk2(acc[cp][1], lo, hi); v0.y = fmaxf(lo + bv0, 0.f); v1.y = fmaxf(hi + bv1, 0.f);
        upk2(acc[cp][2], lo, hi); v0.z = fmaxf(lo + bv0, 0.f); v1.z = fmaxf(hi + bv1, 0.f);
        upk2(acc[cp][3], lo, hi); v0.w = fmaxf(lo + bv0, 0.f); v1.w = fmaxf(hi + bv1, 0.f);
        float* op0 = out + (((size_t)n * COUT + c0    ) * HOUT + oh) * HOUT + ow0;
        float* op1 = out + (((size_t)n * COUT + c0 + 1) * HOUT + oh) * HOUT + ow0;
        *(float4*)op0 = v0;
        *(float4*)op1 = v1;
    }
}

// ---------------- pool over 8x8 spatial AND C=32 heads ----------------
__global__ void pool_kernel()
{
    const int b = blockIdx.x >> 8;
    const int k = blockIdx.x & 255;
    const int p = threadIdx.x;
    float s = 0.0f;
    #pragma unroll
    for (int c = 0; c < CC; c++)
        s += g_h4[(((size_t)(b * CC + c)) * 256 + k) * 64 + p];
    #pragma unroll
    for (int o = 16; o > 0; o >>= 1)
        s += __shfl_xor_sync(0xffffffffu, s, o);
    __shared__ float sh[2];
    if ((p & 31) == 0) sh[p >> 5] = s;
    __syncthreads();
    if (p == 0) g_pbar[b * 256 + k] = (sh[0] + sh[1]) * (1.0f / (CC * 64));
}

// ---------------- FC ----------------
__global__ void fc_kernel(const float* __restrict__ Wfc, const float* __restrict__ bfc,
                          float* __restrict__ out)
{
    const int b = blockIdx.x;
    const int l = threadIdx.x;
    float s = bfc[l];
    const float* p = g_pbar + b * 256;
    #pragma unroll 8
    for (int k = 0; k < 256; k++)
        s = fmaf(p[k], Wfc[k * LATENT + l], s);
    out[b * LATENT + l] = s;
}

// ---------------- launch ----------------
extern "C" void kernel_launch(void* const* d_in, const int* in_sizes, int n_in,
                              void* d_out, int out_size)
{
    const float* x_raw = (const float*)d_in[0];
    const float* W1 = (const float*)d_in[1];  const float* b1 = (const float*)d_in[2];
    const float* W2 = (const float*)d_in[3];  const float* b2 = (const float*)d_in[4];
    const float* W3 = (const float*)d_in[5];  const float* b3 = (const float*)d_in[6];
    const float* W4 = (const float*)d_in[7];  const float* b4 = (const float*)d_in[8];
    const float* Wfc = (const float*)d_in[9]; const float* bfc = (const float*)d_in[10];
    float* out = (float*)d_out;

    float *gaf, *h1, *h2, *h3, *h4, *wr1, *wr2, *wr3, *wr4;
    cudaGetSymbolAddress((void**)&gaf, g_gaf);
    cudaGetSymbolAddress((void**)&h1, g_h1);
    cudaGetSymbolAddress((void**)&h2, g_h2);
    cudaGetSymbolAddress((void**)&h3, g_h3);
    cudaGetSymbolAddress((void**)&h4, g_h4);
    cudaGetSymbolAddress((void**)&wr1, g_wr1);
    cudaGetSymbolAddress((void**)&wr2, g_wr2);
    cudaGetSymbolAddress((void**)&wr3, g_wr3);
    cudaGetSymbolAddress((void**)&wr4, g_wr4);

    gaf_kernel<<<NIMG, 128>>>(x_raw);

    repack_kernel<<<(2*9*32 + 127)/128, 128>>>(W1, wr1, 2, 32);
    repack_kernel<<<(32*9*64 + 127)/128, 128>>>(W2, wr2, 32, 64);
    repack_kernel<<<(64*9*128 + 127)/128, 128>>>(W3, wr3, 64, 128);
    repack_kernel<<<(128*9*256 + 127)/128, 128>>>(W4, wr4, 128, 256);

    // L1: 2->32, 128->64.  strips = 64*16 = 1024, cgroups = 4
    conv2d_s2<2, 128, 32, 128, 1><<<dim3(NIMG, 4, 1024 / 128), 128>>>(gaf, wr1, b1, h1);
    // L2: 32->64, 64->32.  strips = 32*8 = 256, cgroups = 8
    conv2d_s2<32, 64, 64, 128, 1><<<dim3(NIMG, 8, 256 / 128), 128>>>(h1, wr2, b2, h2);
    // L3: 64->128, 32->16. strips = 16*4 = 64, cgroups = 16
    conv2d_s2<64, 32, 128, 64, 2><<<dim3(NIMG, 8, 1), 128>>>(h2, wr3, b3, h3);
    // L4: 128->256, 16->8. strips = 8*2 = 16, cgroups = 32
    conv2d_s2<128, 16, 256, 16, 8><<<dim3(NIMG, 4, 1), 128>>>(h3, wr4, b4, h4);

    pool_kernel<<<BB * 256, 64>>>();
    fc_kernel<<<BB, LATENT>>>(Wfc, bfc, out);
}

// round 5
// speedup vs baseline: 2.5290x; 1.9593x over previous
#include <cuda_runtime.h>
#include <cstdint>
#include <math.h>

// Problem constants
#define BB 16
#define CC 32
#define TT 512
#define SS 128       // GAF_SIZE
#define NIMG (BB*CC) // 512
#define LATENT 128

// ---------------- scratch (no allocation allowed) ----------------
__device__ float g_gaf[(size_t)NIMG * 2 * SS * SS];      // NCHW (input to L1)
__device__ float g_h1 [(size_t)NIMG * 64 * 64 * 32];     // NHWC
__device__ float g_h2 [(size_t)NIMG * 32 * 32 * 64];     // NHWC
__device__ float g_h3 [(size_t)NIMG * 16 * 16 * 128];    // NHWC
__device__ float g_h4 [(size_t)NIMG * 8 * 8 * 256];      // NHWC
__device__ float g_pbar[BB * 256];
__device__ float g_wr1[2 * 9 * 32];                      // L1: [ci][t][cout]
__device__ float g_wr2[(32 * 9)  * 64];                  // [k][cout], k = t*CIN+ci, tf32
__device__ float g_wr3[(64 * 9)  * 128];
__device__ float g_wr4[(128 * 9) * 256];

// ---------------- helpers ----------------
__device__ __forceinline__ uint32_t f2tf32(float f) {
    uint32_t o;
    asm("cvt.rna.tf32.f32 %0, %1;" : "=r"(o) : "f"(f));
    return o;
}
__device__ __forceinline__ void mma_tf32(float* d, const uint32_t* a, const uint32_t* b) {
    asm volatile(
        "mma.sync.aligned.m16n8k8.row.col.f32.tf32.tf32.f32 "
        "{%0,%1,%2,%3}, {%4,%5,%6,%7}, {%8,%9}, {%0,%1,%2,%3};"
        : "+f"(d[0]), "+f"(d[1]), "+f"(d[2]), "+f"(d[3])
        : "r"(a[0]), "r"(a[1]), "r"(a[2]), "r"(a[3]), "r"(b[0]), "r"(b[1]));
}
// ---------------- f32x2 helpers (L1 conv) ----------------
__device__ __forceinline__ unsigned long long pk2(float a, float b) {
    unsigned long long r;
    asm("mov.b64 %0, {%1, %2};" : "=l"(r) : "f"(a), "f"(b));
    return r;
}
__device__ __forceinline__ void upk2(unsigned long long v, float& a, float& b) {
    asm("mov.b64 {%0, %1}, %2;" : "=f"(a), "=f"(b) : "l"(v));
}
__device__ __forceinline__ void fma2(unsigned long long& d, unsigned long long a, unsigned long long b) {
    asm("fma.rn.f32x2 %0, %1, %2, %3;" : "=l"(d) : "l"(a), "l"(b), "l"(d));
}

// ---------------- GAF kernel (NCHW out) ----------------
__global__ void gaf_kernel(const float* __restrict__ x_raw)
{
    const int img = blockIdx.x;
    const int tid = threadIdx.x;   // 0..127
    __shared__ float xs[SS];
    __shared__ float ssq[SS];
    __shared__ float smn[4], smx[4];

    const float4 v4 = *(const float4*)(x_raw + (size_t)img * TT + tid * 4);
    float v = 0.25f * (v4.x + v4.y + v4.z + v4.w);

    float mn = v, mx = v;
    #pragma unroll
    for (int o = 16; o > 0; o >>= 1) {
        mn = fminf(mn, __shfl_xor_sync(0xffffffffu, mn, o));
        mx = fmaxf(mx, __shfl_xor_sync(0xffffffffu, mx, o));
    }
    const int warp = tid >> 5, lane = tid & 31;
    if (lane == 0) { smn[warp] = mn; smx[warp] = mx; }
    __syncthreads();
    mn = fminf(fminf(smn[0], smn[1]), fminf(smn[2], smn[3]));
    mx = fmaxf(fmaxf(smx[0], smx[1]), fmaxf(smx[2], smx[3]));

    float xn = 2.0f * (v - mn) / (mx - mn + 1e-8f) - 1.0f;
    xn = fminf(1.0f, fmaxf(-1.0f, xn));
    float sq = sqrtf(fminf(1.0f, fmaxf(0.0f, 1.0f - xn * xn)));
    xs[tid] = xn;
    ssq[tid] = sq;
    __syncthreads();

    const float xi = xs[tid], si = ssq[tid];
    float* __restrict__ g0 = g_gaf + (size_t)img * (2 * SS * SS) + tid * SS;
    float* __restrict__ g1 = g0 + SS * SS;
    #pragma unroll 4
    for (int j = 0; j < SS; j++) {
        const float xj = xs[j], sj = ssq[j];
        g0[j] = xi * xj - si * sj;
        g1[j] = si * xj - xi * sj;
    }
}

// ---------------- weight repacks ----------------
__global__ void repack_l1(const float* __restrict__ W, float* __restrict__ Wr)
{
    // W[32][2][3][3] -> Wr[ci][t][cout]
    int idx = blockIdx.x * blockDim.x + threadIdx.x;
    if (idx >= 2 * 9 * 32) return;
    int co = idx % 32;
    int t  = (idx / 32) % 9;
    int ci = idx / (32 * 9);
    Wr[idx] = W[((size_t)co * 2 + ci) * 9 + t];
}
__global__ void repack_tc(const float* __restrict__ W, float* __restrict__ Br,
                          int CIN, int COUT)
{
    // W[co][ci][t] -> Br[t*CIN+ci][co], converted to tf32 bit pattern
    int idx = blockIdx.x * blockDim.x + threadIdx.x;
    int K = CIN * 9;
    if (idx >= COUT * K) return;
    int co = idx % COUT;
    int k  = idx / COUT;
    int t  = k / CIN;
    int ci = k % CIN;
    ((uint32_t*)Br)[idx] = f2tf32(W[((size_t)co * CIN + ci) * 9 + t]);
}

// ---------------- L1 direct conv (FFMA2), NCHW in -> NHWC out ----------------
__global__ void __launch_bounds__(128)
conv1_ffma2(const float* __restrict__ in, const float* __restrict__ Wr,
            const float* __restrict__ bias, float* __restrict__ out)
{
    constexpr int CIN = 2, HIN = 128, COUT = 32, HOUT = 64, WQ = 16;
    const int tid  = threadIdx.x;
    const int sid  = tid + blockIdx.z * 128;
    const int n    = blockIdx.x;
    const int cout0 = blockIdx.y * 8;
    const int oh  = sid / WQ;
    const int ow0 = (sid % WQ) * 4;

    const float* __restrict__ inN = in + (size_t)n * CIN * HIN * HIN;

    unsigned long long acc[4][4];
    #pragma unroll
    for (int cp = 0; cp < 4; cp++)
        #pragma unroll
        for (int o = 0; o < 4; o++) acc[cp][o] = 0ull;

    const bool rguard = (ow0 * 2 + 8 < HIN);

    #pragma unroll
    for (int ci = 0; ci < CIN; ci++) {
        const float* __restrict__ wbase = Wr + ((size_t)ci * 9) * COUT + cout0;
        const float* __restrict__ inC = inN + (size_t)ci * HIN * HIN;
        #pragma unroll
        for (int kh = 0; kh < 3; kh++) {
            const int ih = oh * 2 + kh;
            if (ih >= HIN) break;
            const float* row = inC + (size_t)ih * HIN + ow0 * 2;
            float r[9];
            const float4 a = *(const float4*)row;
            const float4 b = *(const float4*)(row + 4);
            r[0]=a.x; r[1]=a.y; r[2]=a.z; r[3]=a.w;
            r[4]=b.x; r[5]=b.y; r[6]=b.z; r[7]=b.w;
            r[8] = rguard ? row[8] : 0.0f;
            unsigned long long pb[9];
            #pragma unroll
            for (int v = 0; v < 9; v++) pb[v] = pk2(r[v], r[v]);
            #pragma unroll
            for (int kw = 0; kw < 3; kw++) {
                const float* wp = wbase + (kh * 3 + kw) * COUT;
                const ulonglong2 wa = *(const ulonglong2*)(wp);
                const ulonglong2 wb = *(const ulonglong2*)(wp + 4);
                #pragma unroll
                for (int o = 0; o < 4; o++) {
                    const unsigned long long x = pb[2 * o + kw];
                    fma2(acc[0][o], wa.x, x);
                    fma2(acc[1][o], wa.y, x);
                    fma2(acc[2][o], wb.x, x);
                    fma2(acc[3][o], wb.y, x);
                }
            }
        }
    }

    float bv[8];
    #pragma unroll
    for (int c = 0; c < 8; c++) bv[c] = __ldg(bias + cout0 + c);
    #pragma unroll
    for (int o = 0; o < 4; o++) {
        float l0,h0,l1,h1,l2,h2,l3,h3;
        upk2(acc[0][o], l0, h0); upk2(acc[1][o], l1, h1);
        upk2(acc[2][o], l2, h2); upk2(acc[3][o], l3, h3);
        float4 vlo, vhi;
        vlo.x = fmaxf(l0 + bv[0], 0.f); vlo.y = fmaxf(h0 + bv[1], 0.f);
        vlo.z = fmaxf(l1 + bv[2], 0.f); vlo.w = fmaxf(h1 + bv[3], 0.f);
        vhi.x = fmaxf(l2 + bv[4], 0.f); vhi.y = fmaxf(h2 + bv[5], 0.f);
        vhi.z = fmaxf(l3 + bv[6], 0.f); vhi.w = fmaxf(h3 + bv[7], 0.f);
        float* op = out + (((size_t)n * HOUT + oh) * HOUT + (ow0 + o)) * COUT + cout0;
        *(float4*)op = vlo;
        *(float4*)(op + 4) = vhi;
    }
}

// ---------------- tf32 mma.sync implicit-GEMM conv (layers 2-4) ----------------
// in: NHWC; Br: [k][COUT] tf32 bits, k = t*CIN+ci; out: NHWC.
// CTA 256 thr, tile M=128 x N=64, warp tile 32x32 (warps 4x2), K chunks of 32,
// double-buffered smem. A stride 36 / B stride 72 floats -> conflict-free LDS.
template<int CIN, int HIN, int COUT>
__global__ void __launch_bounds__(256, 2)
conv_mma(const float* __restrict__ in, const float* __restrict__ Br,
         const float* __restrict__ bias, float* __restrict__ out)
{
    constexpr int HOUT = HIN / 2;
    constexpr int P    = HOUT * HOUT;
    constexpr int K    = CIN * 9;
    constexpr int NCH  = K / 32;
    constexpr int CPT  = CIN / 32;
    constexpr int AST  = 36;            // A smem row stride (floats)
    constexpr int BST  = 72;            // B smem row stride (floats)
    constexpr int AFL  = 128 * AST;     // floats per A buffer
    constexpr int BFL  = 32 * BST;

    extern __shared__ float smf[];
    float* const Abuf[2] = { smf, smf + AFL };
    float* const Bbuf[2] = { smf + 2 * AFL, smf + 2 * AFL + BFL };

    const int tid  = threadIdx.x;
    const int lane = tid & 31;
    const int wid  = tid >> 5;
    const int wm   = wid >> 1;          // 0..3
    const int wn   = wid & 1;           // 0..1
    const int g    = lane >> 2;         // 0..7
    const int tq   = lane & 3;          // 0..3

    // A staging coords: row r = tid>>1, half = tid&1 (16 floats each)
    const int r    = tid >> 1;
    const int half = tid & 1;
    const int pos  = blockIdx.x * 128 + r;
    const int nimg = pos / P;
    const int rem  = pos % P;
    const int oh   = rem / HOUT, ow = rem % HOUT;
    const int ncta = blockIdx.y * 64;

    // B staging coords: row k = tid>>3, col4 = (tid&7)*8 (8 floats)
    const int bk  = tid >> 3;
    const int bc  = (tid & 7) * 8;

    float4 av[4];
    float4 bv[2];

    auto ldg_chunk = [&](int kc) {
        const int t   = kc / CPT;
        const int ci0 = (kc % CPT) * 32;
        const int kh = t / 3, kw = t % 3;
        const int ih = oh * 2 + kh, iw = ow * 2 + kw;
        if (ih < HIN && iw < HIN) {
            const float* s = in + ((((size_t)nimg * HIN + ih) * HIN + iw) * CIN + ci0) + half * 16;
            av[0] = *(const float4*)(s);
            av[1] = *(const float4*)(s + 4);
            av[2] = *(const float4*)(s + 8);
            av[3] = *(const float4*)(s + 12);
        } else {
            av[0] = av[1] = av[2] = av[3] = make_float4(0.f, 0.f, 0.f, 0.f);
        }
        const float* sB = Br + ((size_t)(kc * 32 + bk)) * COUT + ncta + bc;
        bv[0] = *(const float4*)(sB);
        bv[1] = *(const float4*)(sB + 4);
    };
    auto sts_chunk = [&](int buf) {
        float* A = Abuf[buf] + r * AST + half * 16;
        #pragma unroll
        for (int q = 0; q < 4; q++) {
            const float* f = (const float*)&av[q];
            uint4 u;
            u.x = f2tf32(f[0]); u.y = f2tf32(f[1]);
            u.z = f2tf32(f[2]); u.w = f2tf32(f[3]);
            *(uint4*)(A + q * 4) = u;
        }
        float* Bp = Bbuf[buf] + bk * BST + bc;
        *(float4*)(Bp)     = bv[0];
        *(float4*)(Bp + 4) = bv[1];
    };

    ldg_chunk(0);
    sts_chunk(0);
    __syncthreads();

    float d[2][4][4];
    #pragma unroll
    for (int mf = 0; mf < 2; mf++)
        #pragma unroll
        for (int nf = 0; nf < 4; nf++)
            #pragma unroll
            for (int j = 0; j < 4; j++) d[mf][nf][j] = 0.f;

    for (int c = 0; c < NCH; c++) {
        const int buf = c & 1;
        if (c + 1 < NCH) ldg_chunk(c + 1);

        const uint32_t* A = (const uint32_t*)Abuf[buf];
        const uint32_t* B = (const uint32_t*)Bbuf[buf];
        #pragma unroll
        for (int ks = 0; ks < 4; ks++) {
            uint32_t a[2][4], b[4][2];
            const int ac = ks * 8 + tq;
            #pragma unroll
            for (int mf = 0; mf < 2; mf++) {
                const int ar = wm * 32 + mf * 16 + g;
                a[mf][0] = A[ar * AST + ac];
                a[mf][1] = A[(ar + 8) * AST + ac];
                a[mf][2] = A[ar * AST + ac + 4];
                a[mf][3] = A[(ar + 8) * AST + ac + 4];
            }
            const int bkr = ks * 8 + tq;
            #pragma unroll
            for (int nf = 0; nf < 4; nf++) {
                const int bcc = wn * 32 + nf * 8 + g;
                b[nf][0] = B[bkr * BST + bcc];
                b[nf][1] = B[(bkr + 4) * BST + bcc];
            }
            #pragma unroll
            for (int mf = 0; mf < 2; mf++)
                #pragma unroll
                for (int nf = 0; nf < 4; nf++)
                    mma_tf32(d[mf][nf], a[mf], b[nf]);
        }

        if (c + 1 < NCH) sts_chunk(buf ^ 1);
        __syncthreads();
    }

    // epilogue: bias + ReLU, NHWC stores (float2 per fragment row)
    #pragma unroll
    for (int nf = 0; nf < 4; nf++) {
        const int col = ncta + wn * 32 + nf * 8 + 2 * tq;
        const float b0 = __ldg(bias + col);
        const float b1 = __ldg(bias + col + 1);
        #pragma unroll
        for (int mf = 0; mf < 2; mf++) {
            const int row0 = blockIdx.x * 128 + wm * 32 + mf * 16 + g;
            float2 v0, v1;
            v0.x = fmaxf(d[mf][nf][0] + b0, 0.f);
            v0.y = fmaxf(d[mf][nf][1] + b1, 0.f);
            v1.x = fmaxf(d[mf][nf][2] + b0, 0.f);
            v1.y = fmaxf(d[mf][nf][3] + b1, 0.f);
            *(float2*)(out + (size_t)row0 * COUT + col)       = v0;
            *(float2*)(out + (size_t)(row0 + 8) * COUT + col) = v1;
        }
    }
}

// ---------------- pool: h4 NHWC [img][8][8][256] -> pbar[16][256] ----------------
__global__ void pool_kernel()
{
    const int b = blockIdx.x;
    const int k = threadIdx.x;  // 0..255
    const float* __restrict__ base = g_h4 + (size_t)b * CC * 64 * 256 + k;
    float s = 0.0f;
    #pragma unroll 8
    for (int i = 0; i < CC * 64; i++)
        s += base[(size_t)i * 256];
    g_pbar[b * 256 + k] = s * (1.0f / (CC * 64));
}

// ---------------- FC ----------------
__global__ void fc_kernel(const float* __restrict__ Wfc, const float* __restrict__ bfc,
                          float* __restrict__ out)
{
    const int b = blockIdx.x;
    const int l = threadIdx.x;
    float s = bfc[l];
    const float* p = g_pbar + b * 256;
    #pragma unroll 8
    for (int k = 0; k < 256; k++)
        s = fmaf(p[k], Wfc[k * LATENT + l], s);
    out[b * LATENT + l] = s;
}

// ---------------- launch ----------------
extern "C" void kernel_launch(void* const* d_in, const int* in_sizes, int n_in,
                              void* d_out, int out_size)
{
    const float* x_raw = (const float*)d_in[0];
    const float* W1 = (const float*)d_in[1];  const float* b1 = (const float*)d_in[2];
    const float* W2 = (const float*)d_in[3];  const float* b2 = (const float*)d_in[4];
    const float* W3 = (const float*)d_in[5];  const float* b3 = (const float*)d_in[6];
    const float* W4 = (const float*)d_in[7];  const float* b4 = (const float*)d_in[8];
    const float* Wfc = (const float*)d_in[9]; const float* bfc = (const float*)d_in[10];
    float* out = (float*)d_out;

    float *gaf, *h1, *h2, *h3, *h4, *wr1, *wr2, *wr3, *wr4;
    cudaGetSymbolAddress((void**)&gaf, g_gaf);
    cudaGetSymbolAddress((void**)&h1, g_h1);
    cudaGetSymbolAddress((void**)&h2, g_h2);
    cudaGetSymbolAddress((void**)&h3, g_h3);
    cudaGetSymbolAddress((void**)&h4, g_h4);
    cudaGetSymbolAddress((void**)&wr1, g_wr1);
    cudaGetSymbolAddress((void**)&wr2, g_wr2);
    cudaGetSymbolAddress((void**)&wr3, g_wr3);
    cudaGetSymbolAddress((void**)&wr4, g_wr4);

    // dynamic smem: 2*A(18432B) + 2*B(9216B) = 55296B
    const int smemB = 2 * (128 * 36 * 4) + 2 * (32 * 72 * 4);
    cudaFuncSetAttribute(conv_mma<32, 64, 64>,   cudaFuncAttributeMaxDynamicSharedMemorySize, smemB);
    cudaFuncSetAttribute(conv_mma<64, 32, 128>,  cudaFuncAttributeMaxDynamicSharedMemorySize, smemB);
    cudaFuncSetAttribute(conv_mma<128, 16, 256>, cudaFuncAttributeMaxDynamicSharedMemorySize, smemB);

    gaf_kernel<<<NIMG, 128>>>(x_raw);

    repack_l1<<<(2*9*32 + 127)/128, 128>>>(W1, wr1);
    repack_tc<<<(64*32*9  + 127)/128, 128>>>(W2, wr2, 32, 64);
    repack_tc<<<(128*64*9 + 127)/128, 128>>>(W3, wr3, 64, 128);
    repack_tc<<<(256*128*9 + 127)/128, 128>>>(W4, wr4, 128, 256);

    // L1: FFMA2 direct conv, NCHW -> NHWC
    conv1_ffma2<<<dim3(NIMG, 4, 8), 128>>>(gaf, wr1, b1, h1);

    // L2-L4: tf32 mma.sync implicit GEMM
    conv_mma<32, 64, 64>  <<<dim3(NIMG * 1024 / 128, 1), 256, smemB>>>(h1, wr2, b2, h2);
    conv_mma<64, 32, 128> <<<dim3(NIMG * 256  / 128, 2), 256, smemB>>>(h2, wr3, b3, h3);
    conv_mma<128, 16, 256><<<dim3(NIMG * 64   / 128, 4), 256, smemB>>>(h3, wr4, b4, h4);

    pool_kernel<<<BB, 256>>>();
    fc_kernel<<<BB, LATENT>>>(Wfc, bfc, out);
}

// round 7
// speedup vs baseline: 2.7765x; 1.0979x over previous
#include <cuda_runtime.h>
#include <cstdint>
#include <math.h>

// Problem constants
#define BB 16
#define CC 32
#define TT 512
#define SS 128       // GAF_SIZE
#define NIMG (BB*CC) // 512
#define LATENT 128

// ---------------- scratch (no allocation allowed) ----------------
__device__ float g_gaf[(size_t)NIMG * 2 * SS * SS];      // NCHW (input to L1)
__device__ float g_h1 [(size_t)NIMG * 64 * 64 * 32];     // NHWC, tf32-rounded
__device__ float g_h2 [(size_t)NIMG * 32 * 32 * 64];     // NHWC, tf32-rounded
__device__ float g_h3 [(size_t)NIMG * 16 * 16 * 128];    // NHWC, tf32-rounded
__device__ float g_h4 [(size_t)NIMG * 8 * 8 * 256];      // NHWC, fp32
__device__ float g_pp  [NIMG * 256];
__device__ float g_pbar[BB * 256];
__device__ float g_wr1[2 * 9 * 32];                      // L1: [ci][t][cout]
__device__ float g_wr2[(32 * 9)  * 64];                  // [k][cout], tf32 bits
__device__ float g_wr3[(64 * 9)  * 128];
__device__ float g_wr4[(128 * 9) * 256];

// ---------------- helpers ----------------
__device__ __forceinline__ uint32_t f2tf32(float f) {
    uint32_t o;
    asm("cvt.rna.tf32.f32 %0, %1;" : "=r"(o) : "f"(f));
    return o;
}
__device__ __forceinline__ float f2tf32f(float f) {
    return __uint_as_float(f2tf32(f));
}
__device__ __forceinline__ void mma_tf32(float* d, const uint32_t* a, const uint32_t* b) {
    asm volatile(
        "mma.sync.aligned.m16n8k8.row.col.f32.tf32.tf32.f32 "
        "{%0,%1,%2,%3}, {%4,%5,%6,%7}, {%8,%9}, {%0,%1,%2,%3};"
        : "+f"(d[0]), "+f"(d[1]), "+f"(d[2]), "+f"(d[3])
        : "r"(a[0]), "r"(a[1]), "r"(a[2]), "r"(a[3]), "r"(b[0]), "r"(b[1]));
}
__device__ __forceinline__ uint32_t smem_u32(const void* p) {
    uint32_t a;
    asm("{ .reg .u64 t; cvta.to.shared.u64 t, %1; cvt.u32.u64 %0, t; }" : "=r"(a) : "l"(p));
    return a;
}
__device__ __forceinline__ void cpasync16(uint32_t dst, const void* src, int srcsize) {
    asm volatile("cp.async.cg.shared.global [%0], [%1], 16, %2;"
                 :: "r"(dst), "l"(src), "r"(srcsize) : "memory");
}
#define CP_COMMIT() asm volatile("cp.async.commit_group;" ::: "memory")
#define CP_WAIT1()  asm volatile("cp.async.wait_group 1;" ::: "memory")
#define CP_WAIT0()  asm volatile("cp.async.wait_group 0;" ::: "memory")

// ---------------- f32x2 helpers (L1 conv) ----------------
__device__ __forceinline__ unsigned long long pk2(float a, float b) {
    unsigned long long r;
    asm("mov.b64 %0, {%1, %2};" : "=l"(r) : "f"(a), "f"(b));
    return r;
}
__device__ __forceinline__ void upk2(unsigned long long v, float& a, float& b) {
    asm("mov.b64 {%0, %1}, %2;" : "=f"(a), "=f"(b) : "l"(v));
}
__device__ __forceinline__ void fma2(unsigned long long& d, unsigned long long a, unsigned long long b) {
    asm("fma.rn.f32x2 %0, %1, %2, %3;" : "=l"(d) : "l"(a), "l"(b), "l"(d));
}

// ---------------- merged weight repack ----------------
__device__ __forceinline__ void rp_tc(const float* __restrict__ W, uint32_t* __restrict__ Br,
                                      int CIN, int COUT, int idx)
{
    int co = idx % COUT;
    int k  = idx / COUT;
    int t  = k / CIN;
    int ci = k % CIN;
    Br[idx] = f2tf32(W[((size_t)co * CIN + ci) * 9 + t]);
}
__global__ void repack_all(const float* __restrict__ W1, const float* __restrict__ W2,
                           const float* __restrict__ W3, const float* __restrict__ W4)
{
    int idx = blockIdx.x * blockDim.x + threadIdx.x;
    if (idx < 576) {                       // L1: W[32][2][3][3] -> [ci][t][cout]
        int co = idx % 32;
        int t  = (idx / 32) % 9;
        int ci = idx / (32 * 9);
        g_wr1[idx] = W1[((size_t)co * 2 + ci) * 9 + t];
        return;
    }
    idx -= 576;
    if (idx < 288 * 64)  { rp_tc(W2, (uint32_t*)g_wr2, 32, 64, idx);  return; }
    idx -= 288 * 64;
    if (idx < 576 * 128) { rp_tc(W3, (uint32_t*)g_wr3, 64, 128, idx); return; }
    idx -= 576 * 128;
    if (idx < 1152 * 256) rp_tc(W4, (uint32_t*)g_wr4, 128, 256, idx);
}

// ---------------- GAF kernel (NCHW out), coalesced row stores ----------------
__global__ void gaf_kernel(const float* __restrict__ x_raw)
{
    const int img = blockIdx.x;
    const int tid = threadIdx.x;   // 0..127
    __shared__ float xs[SS];
    __shared__ float ssq[SS];
    __shared__ float smn[4], smx[4];

    const float4 v4 = *(const float4*)(x_raw + (size_t)img * TT + tid * 4);
    float v = 0.25f * (v4.x + v4.y + v4.z + v4.w);

    float mn = v, mx = v;
    #pragma unroll
    for (int o = 16; o > 0; o >>= 1) {
        mn = fminf(mn, __shfl_xor_sync(0xffffffffu, mn, o));
        mx = fmaxf(mx, __shfl_xor_sync(0xffffffffu, mx, o));
    }
    const int warp = tid >> 5, lane = tid & 31;
    if (lane == 0) { smn[warp] = mn; smx[warp] = mx; }
    __syncthreads();
    mn = fminf(fminf(smn[0], smn[1]), fminf(smn[2], smn[3]));
    mx = fmaxf(fmaxf(smx[0], smx[1]), fmaxf(smx[2], smx[3]));

    float xn = 2.0f * (v - mn) / (mx - mn + 1e-8f) - 1.0f;
    xn = fminf(1.0f, fmaxf(-1.0f, xn));
    float sq = sqrtf(fminf(1.0f, fmaxf(0.0f, 1.0f - xn * xn)));
    xs[tid] = xn;
    ssq[tid] = sq;
    __syncthreads();

    // warp-per-row, float4 columns: fully coalesced 512B stores per row
    const int c0 = lane * 4;
    float xj[4], sj[4];
    #pragma unroll
    for (int c = 0; c < 4; c++) { xj[c] = xs[c0 + c]; sj[c] = ssq[c0 + c]; }
    float* __restrict__ g0 = g_gaf + (size_t)img * (2 * SS * SS);
    float* __restrict__ g1 = g0 + SS * SS;
    for (int rb = 0; rb < SS; rb += 4) {
        const int row = rb + warp;
        const float xi = xs[row], si = ssq[row];
        float4 o0, o1;
        o0.x = xi * xj[0] - si * sj[0];  o1.x = si * xj[0] - xi * sj[0];
        o0.y = xi * xj[1] - si * sj[1];  o1.y = si * xj[1] - xi * sj[1];
        o0.z = xi * xj[2] - si * sj[2];  o1.z = si * xj[2] - xi * sj[2];
        o0.w = xi * xj[3] - si * sj[3];  o1.w = si * xj[3] - xi * sj[3];
        *(float4*)(g0 + row * SS + c0) = o0;
        *(float4*)(g1 + row * SS + c0) = o1;
    }
}

// ---------------- L1 direct conv (FFMA2), NCHW in -> NHWC out (tf32-rounded) --------
__global__ void __launch_bounds__(128)
conv1_ffma2(const float* __restrict__ in, const float* __restrict__ Wr,
            const float* __restrict__ bias, float* __restrict__ out)
{
    constexpr int CIN = 2, HIN = 128, COUT = 32, HOUT = 64, WQ = 16;
    const int tid  = threadIdx.x;
    const int sid  = tid + blockIdx.z * 128;
    const int n    = blockIdx.x;
    const int cout0 = blockIdx.y * 8;
    const int oh  = sid / WQ;
    const int ow0 = (sid % WQ) * 4;

    const float* __restrict__ inN = in + (size_t)n * CIN * HIN * HIN;

    unsigned long long acc[4][4];
    #pragma unroll
    for (int cp = 0; cp < 4; cp++)
        #pragma unroll
        for (int o = 0; o < 4; o++) acc[cp][o] = 0ull;

    const bool rguard = (ow0 * 2 + 8 < HIN);

    #pragma unroll
    for (int ci = 0; ci < CIN; ci++) {
        const float* __restrict__ wbase = Wr + ((size_t)ci * 9) * COUT + cout0;
        const float* __restrict__ inC = inN + (size_t)ci * HIN * HIN;
        #pragma unroll
        for (int kh = 0; kh < 3; kh++) {
            const int ih = oh * 2 + kh;
            if (ih >= HIN) break;
            const float* row = inC + (size_t)ih * HIN + ow0 * 2;
            float r[9];
            const float4 a = *(const float4*)row;
            const float4 b = *(const float4*)(row + 4);
            r[0]=a.x; r[1]=a.y; r[2]=a.z; r[3]=a.w;
            r[4]=b.x; r[5]=b.y; r[6]=b.z; r[7]=b.w;
            r[8] = rguard ? row[8] : 0.0f;
            unsigned long long pb[9];
            #pragma unroll
            for (int v = 0; v < 9; v++) pb[v] = pk2(r[v], r[v]);
            #pragma unroll
            for (int kw = 0; kw < 3; kw++) {
                const float* wp = wbase + (kh * 3 + kw) * COUT;
                const ulonglong2 wa = *(const ulonglong2*)(wp);
                const ulonglong2 wb = *(const ulonglong2*)(wp + 4);
                #pragma unroll
                for (int o = 0; o < 4; o++) {
                    const unsigned long long x = pb[2 * o + kw];
                    fma2(acc[0][o], wa.x, x);
                    fma2(acc[1][o], wa.y, x);
                    fma2(acc[2][o], wb.x, x);
                    fma2(acc[3][o], wb.y, x);
                }
            }
        }
    }

    float bv[8];
    #pragma unroll
    for (int c = 0; c < 8; c++) bv[c] = __ldg(bias + cout0 + c);
    #pragma unroll
    for (int o = 0; o < 4; o++) {
        float l0,h0,l1,h1,l2,h2,l3,h3;
        upk2(acc[0][o], l0, h0); upk2(acc[1][o], l1, h1);
        upk2(acc[2][o], l2, h2); upk2(acc[3][o], l3, h3);
        float4 vlo, vhi;   // tf32-round outputs so downstream MMA truncation is exact
        vlo.x = f2tf32f(fmaxf(l0 + bv[0], 0.f)); vlo.y = f2tf32f(fmaxf(h0 + bv[1], 0.f));
        vlo.z = f2tf32f(fmaxf(l1 + bv[2], 0.f)); vlo.w = f2tf32f(fmaxf(h1 + bv[3], 0.f));
        vhi.x = f2tf32f(fmaxf(l2 + bv[4], 0.f)); vhi.y = f2tf32f(fmaxf(h2 + bv[5], 0.f));
        vhi.z = f2tf32f(fmaxf(l3 + bv[6], 0.f)); vhi.w = f2tf32f(fmaxf(h3 + bv[7], 0.f));
        float* op = out + (((size_t)n * HOUT + oh) * HOUT + (ow0 + o)) * COUT + cout0;
        *(float4*)op = vlo;
        *(float4*)(op + 4) = vhi;
    }
}

// ---------------- tf32 mma.sync implicit-GEMM conv, cp.async pipeline ----------------
// in: NHWC (tf32-rounded); Br: [k][COUT] tf32 bits; out: NHWC.
// CTA 256 thr, tile M=TM x N=COUT, K chunks of 32, double-buffered cp.async.
// CVTOUT: round outputs to tf32 (for layers feeding another MMA).
template<int CIN, int HIN, int COUT, int TM, bool CVTOUT>
__global__ void __launch_bounds__(256)
conv_mma(const float* __restrict__ in, const float* __restrict__ Br,
         const float* __restrict__ bias, float* __restrict__ out)
{
    constexpr int HOUT = HIN / 2;
    constexpr int P    = HOUT * HOUT;
    constexpr int K    = CIN * 9;
    constexpr int NCH  = K / 32;
    constexpr int CPT  = CIN / 32;
    constexpr int WM   = TM / 32;         // warps along M
    constexpr int WN   = 8 / WM;          // warps along N
    constexpr int WNT  = COUT / WN;       // warp n-tile
    constexpr int NF   = WNT / 8;         // n fragments per warp
    constexpr int AST  = 36;              // A smem row stride (floats)
    constexpr int BST  = COUT + 8;        // B smem row stride (floats), ≡8 mod 32
    constexpr int AFL  = TM * AST;
    constexpr int BFL  = 32 * BST;
    constexpr int TPR  = 256 / TM;        // threads per A row
    constexpr int CHK  = 8 / TPR;         // 16B chunks per thread (A row = 8 chunks)

    extern __shared__ float smf[];
    float* const Ab[2] = { smf, smf + AFL };
    float* const Bb[2] = { smf + 2 * AFL, smf + 2 * AFL + BFL };

    const int tid  = threadIdx.x;
    const int lane = tid & 31;
    const int wid  = tid >> 5;
    const int wm   = wid % WM;
    const int wn   = wid / WM;
    const int g    = lane >> 2;           // 0..7
    const int tq   = lane & 3;            // 0..3

    // A staging coords
    const int r    = tid / TPR;
    const int sub  = tid % TPR;
    const int pos  = blockIdx.x * TM + r;
    const int nimg = pos / P;
    const int rem  = pos % P;
    const int oh   = rem / HOUT, ow = rem % HOUT;

    uint32_t a_s[2], b_s[2];
    a_s[0] = smem_u32(Ab[0]); a_s[1] = smem_u32(Ab[1]);
    b_s[0] = smem_u32(Bb[0]); b_s[1] = smem_u32(Bb[1]);
    const uint32_t a_dst_off = (r * AST + sub * CHK * 4) * 4;

    auto prefetch = [&](int kc, int buf) {
        const int t   = kc / CPT;
        const int ci0 = (kc % CPT) * 32;
        const int kh = t / 3, kw = t % 3;
        const int ih = oh * 2 + kh, iw = ow * 2 + kw;
        const bool val = (ih < HIN) && (iw < HIN);
        const float* s = val
            ? in + ((((size_t)nimg * HIN + ih) * HIN + iw) * CIN + ci0) + sub * CHK * 4
            : in;
        const int sz = val ? 16 : 0;
        const uint32_t ad = a_s[buf] + a_dst_off;
        #pragma unroll
        for (int c = 0; c < CHK; c++)
            cpasync16(ad + c * 16, s + c * 4, sz);
        // B: 32 rows x COUT floats
        const float* bsrc = Br + (size_t)(kc * 32) * COUT;
        #pragma unroll
        for (int j = 0; j < COUT / 32; j++) {
            const int cid = j * 256 + tid;
            const int k   = cid / (COUT / 4);
            const int cc  = cid % (COUT / 4);
            cpasync16(b_s[buf] + (k * BST + cc * 4) * 4, bsrc + (size_t)k * COUT + cc * 4, 16);
        }
    };

    prefetch(0, 0);
    CP_COMMIT();

    float d[2][NF][4];
    #pragma unroll
    for (int mf = 0; mf < 2; mf++)
        #pragma unroll
        for (int nf = 0; nf < NF; nf++)
            #pragma unroll
            for (int j = 0; j < 4; j++) d[mf][nf][j] = 0.f;

    for (int c = 0; c < NCH; c++) {
        const int buf = c & 1;
        if (c + 1 < NCH) {
            prefetch(c + 1, buf ^ 1);
            CP_COMMIT();
            CP_WAIT1();
        } else {
            CP_WAIT0();
        }
        __syncthreads();

        const uint32_t* A = (const uint32_t*)Ab[buf];
        const uint32_t* B = (const uint32_t*)Bb[buf];
        #pragma unroll
        for (int ks = 0; ks < 4; ks++) {
            uint32_t a[2][4], b[NF][2];
            const int ac = ks * 8 + tq;
            #pragma unroll
            for (int mf = 0; mf < 2; mf++) {
                const int ar = wm * 32 + mf * 16 + g;
                a[mf][0] = A[ar * AST + ac];
                a[mf][1] = A[(ar + 8) * AST + ac];
                a[mf][2] = A[ar * AST + ac + 4];
                a[mf][3] = A[(ar + 8) * AST + ac + 4];
            }
            const int bkr = ks * 8 + tq;
            #pragma unroll
            for (int nf = 0; nf < NF; nf++) {
                const int bcc = wn * WNT + nf * 8 + g;
                b[nf][0] = B[bkr * BST + bcc];
                b[nf][1] = B[(bkr + 4) * BST + bcc];
            }
            #pragma unroll
            for (int mf = 0; mf < 2; mf++)
                #pragma unroll
                for (int nf = 0; nf < NF; nf++)
                    mma_tf32(d[mf][nf], a[mf], b[nf]);
        }
        __syncthreads();
    }

    // epilogue: bias + ReLU (+ optional tf32 round), NHWC float2 stores
    #pragma unroll
    for (int nf = 0; nf < NF; nf++) {
        const int col = wn * WNT + nf * 8 + 2 * tq;
        const float b0 = __ldg(bias + col);
        const float b1 = __ldg(bias + col + 1);
        #pragma unroll
        for (int mf = 0; mf < 2; mf++) {
            const int row0 = blockIdx.x * TM + wm * 32 + mf * 16 + g;
            float2 v0, v1;
            v0.x = fmaxf(d[mf][nf][0] + b0, 0.f);
            v0.y = fmaxf(d[mf][nf][1] + b1, 0.f);
            v1.x = fmaxf(d[mf][nf][2] + b0, 0.f);
            v1.y = fmaxf(d[mf][nf][3] + b1, 0.f);
            if (CVTOUT) {
                v0.x = f2tf32f(v0.x); v0.y = f2tf32f(v0.y);
                v1.x = f2tf32f(v1.x); v1.y = f2tf32f(v1.y);
            }
            *(float2*)(out + (size_t)row0 * COUT + col)       = v0;
            *(float2*)(out + (size_t)(row0 + 8) * COUT + col) = v1;
        }
    }
}

// ---------------- pool stage 1: per image, sum 64 positions ----------------
__global__ void pool1()
{
    const int img = blockIdx.x;
    const int k = threadIdx.x;  // 0..255
    const float* __restrict__ base = g_h4 + (size_t)img * 64 * 256 + k;
    float s = 0.0f;
    #pragma unroll
    for (int i = 0; i < 64; i++)
        s += base[(size_t)i * 256];
    g_pp[img * 256 + k] = s;
}
// ---------------- pool stage 2: sum over C=32 heads ----------------
__global__ void pool2()
{
    const int b = blockIdx.x;
    const int k = threadIdx.x;
    const float* __restrict__ p = g_pp + (size_t)b * 32 * 256 + k;
    float s = 0.0f;
    #pragma unroll
    for (int c = 0; c < 32; c++)
        s += p[(size_t)c * 256];
    g_pbar[b * 256 + k] = s * (1.0f / 2048.0f);
}

// ---------------- FC ----------------
__global__ void fc_kernel(const float* __restrict__ Wfc, const float* __restrict__ bfc,
                          float* __restrict__ out)
{
    const int b = blockIdx.x;
    const int l = threadIdx.x;
    float s = bfc[l];
    const float* p = g_pbar + b * 256;
    #pragma unroll 8
    for (int k = 0; k < 256; k++)
        s = fmaf(p[k], Wfc[k * LATENT + l], s);
    out[b * LATENT + l] = s;
}

// ---------------- launch ----------------
extern "C" void kernel_launch(void* const* d_in, const int* in_sizes, int n_in,
                              void* d_out, int out_size)
{
    const float* x_raw = (const float*)d_in[0];
    const float* W1 = (const float*)d_in[1];  const float* b1 = (const float*)d_in[2];
    const float* W2 = (const float*)d_in[3];  const float* b2 = (const float*)d_in[4];
    const float* W3 = (const float*)d_in[5];  const float* b3 = (const float*)d_in[6];
    const float* W4 = (const float*)d_in[7];  const float* b4 = (const float*)d_in[8];
    const float* Wfc = (const float*)d_in[9]; const float* bfc = (const float*)d_in[10];
    float* out = (float*)d_out;

    float *gaf, *h1, *h2, *h3, *h4, *wr1, *wr2, *wr3, *wr4;
    cudaGetSymbolAddress((void**)&gaf, g_gaf);
    cudaGetSymbolAddress((void**)&h1, g_h1);
    cudaGetSymbolAddress((void**)&h2, g_h2);
    cudaGetSymbolAddress((void**)&h3, g_h3);
    cudaGetSymbolAddress((void**)&h4, g_h4);
    cudaGetSymbolAddress((void**)&wr1, g_wr1);
    cudaGetSymbolAddress((void**)&wr2, g_wr2);
    cudaGetSymbolAddress((void**)&wr3, g_wr3);
    cudaGetSymbolAddress((void**)&wr4, g_wr4);

    const int smem2 = 2 * (128 * 36 + 32 * 72)  * 4;   // 55296
    const int smem3 = 2 * (128 * 36 + 32 * 136) * 4;   // 71680
    const int smem4 = 2 * (64  * 36 + 32 * 264) * 4;   // 86016
    cudaFuncSetAttribute(conv_mma<32, 64, 64, 128, true>,    cudaFuncAttributeMaxDynamicSharedMemorySize, smem2);
    cudaFuncSetAttribute(conv_mma<64, 32, 128, 128, true>,   cudaFuncAttributeMaxDynamicSharedMemorySize, smem3);
    cudaFuncSetAttribute(conv_mma<128, 16, 256, 64, false>,  cudaFuncAttributeMaxDynamicSharedMemorySize, smem4);

    const int rp_total = 576 + 288 * 64 + 576 * 128 + 1152 * 256;

    // launch order chosen so the ncu-profiled slot lands on conv_mma L3
    repack_all<<<(rp_total + 255) / 256, 256>>>(W1, W2, W3, W4);       // 0
    gaf_kernel<<<NIMG, 128>>>(x_raw);                                  // 1
    conv1_ffma2<<<dim3(NIMG, 4, 8), 128>>>(gaf, wr1, b1, h1);          // 2
    conv_mma<32, 64, 64, 128, true>  <<<NIMG * 1024 / 128, 256, smem2>>>(h1, wr2, b2, h2);  // 3
    conv_mma<64, 32, 128, 128, true> <<<NIMG * 256  / 128, 256, smem3>>>(h2, wr3, b3, h3);  // 4 (profiled)
    conv_mma<128, 16, 256, 64, false><<<NIMG * 64   / 64,  256, smem4>>>(h3, wr4, b4, h4);  // 5
    pool1<<<NIMG, 256>>>();                                            // 6
    pool2<<<BB, 256>>>();                                              // 7
    fc_kernel<<<BB, LATENT>>>(Wfc, bfc, out);                          // 8
}

// round 8
// speedup vs baseline: 4.1245x; 1.4855x over previous
#include <cuda_runtime.h>
#include <cstdint>
#include <math.h>

// Problem constants
#define BB 16
#define CC 32
#define TT 512
#define SS 128       // GAF_SIZE
#define NIMG (BB*CC) // 512
#define LATENT 128

// ---------------- scratch (no allocation allowed) ----------------
__device__ float g_gaf[(size_t)NIMG * 2 * SS * SS];      // NCHW (input to L1)
__device__ float g_h1 [(size_t)NIMG * 64 * 64 * 32];     // NHWC, tf32-rounded
__device__ float g_h2 [(size_t)NIMG * 32 * 32 * 64];     // NHWC, tf32-rounded
__device__ float g_h3 [(size_t)NIMG * 16 * 16 * 128];    // NHWC, tf32-rounded
__device__ float g_h4 [(size_t)NIMG * 8 * 8 * 256];      // NHWC, fp32
__device__ float g_pp  [NIMG * 256];
__device__ float g_pbar[BB * 256];
__device__ float g_wr1[2 * 9 * 32];                      // L1: [ci][t][cout]
__device__ float g_wr2[(32 * 9)  * 64];                  // [k][cout], tf32 bits
__device__ float g_wr3[(64 * 9)  * 128];
__device__ float g_wr4[(128 * 9) * 256];

// ---------------- helpers ----------------
__device__ __forceinline__ uint32_t f2tf32(float f) {
    uint32_t o;
    asm("cvt.rna.tf32.f32 %0, %1;" : "=r"(o) : "f"(f));
    return o;
}
__device__ __forceinline__ float f2tf32f(float f) {
    return __uint_as_float(f2tf32(f));
}
__device__ __forceinline__ void mma_tf32(float* d, const uint32_t* a, const uint32_t* b) {
    asm volatile(
        "mma.sync.aligned.m16n8k8.row.col.f32.tf32.tf32.f32 "
        "{%0,%1,%2,%3}, {%4,%5,%6,%7}, {%8,%9}, {%0,%1,%2,%3};"
        : "+f"(d[0]), "+f"(d[1]), "+f"(d[2]), "+f"(d[3])
        : "r"(a[0]), "r"(a[1]), "r"(a[2]), "r"(a[3]), "r"(b[0]), "r"(b[1]));
}
__device__ __forceinline__ uint32_t smem_u32(const void* p) {
    uint32_t a;
    asm("{ .reg .u64 t; cvta.to.shared.u64 t, %1; cvt.u32.u64 %0, t; }" : "=r"(a) : "l"(p));
    return a;
}
__device__ __forceinline__ void cpasync16(uint32_t dst, const void* src, int srcsize) {
    asm volatile("cp.async.cg.shared.global [%0], [%1], 16, %2;"
                 :: "r"(dst), "l"(src), "r"(srcsize) : "memory");
}
#define CP_COMMIT() asm volatile("cp.async.commit_group;" ::: "memory")
#define CP_WAIT1()  asm volatile("cp.async.wait_group 1;" ::: "memory")
#define CP_WAIT0()  asm volatile("cp.async.wait_group 0;" ::: "memory")

// ---------------- f32x2 helpers (L1 conv) ----------------
__device__ __forceinline__ unsigned long long pk2(float a, float b) {
    unsigned long long r;
    asm("mov.b64 %0, {%1, %2};" : "=l"(r) : "f"(a), "f"(b));
    return r;
}
__device__ __forceinline__ void upk2(unsigned long long v, float& a, float& b) {
    asm("mov.b64 {%0, %1}, %2;" : "=f"(a), "=f"(b) : "l"(v));
}
__device__ __forceinline__ void fma2(unsigned long long& d, unsigned long long a, unsigned long long b) {
    asm("fma.rn.f32x2 %0, %1, %2, %3;" : "=l"(d) : "l"(a), "l"(b), "l"(d));
}

// ---------------- merged weight repack ----------------
__device__ __forceinline__ void rp_tc(const float* __restrict__ W, uint32_t* __restrict__ Br,
                                      int CIN, int COUT, int idx)
{
    int co = idx % COUT;
    int k  = idx / COUT;
    int t  = k / CIN;
    int ci = k % CIN;
    Br[idx] = f2tf32(W[((size_t)co * CIN + ci) * 9 + t]);
}
__global__ void repack_all(const float* __restrict__ W1, const float* __restrict__ W2,
                           const float* __restrict__ W3, const float* __restrict__ W4)
{
    int idx = blockIdx.x * blockDim.x + threadIdx.x;
    if (idx < 576) {                       // L1: W[32][2][3][3] -> [ci][t][cout]
        int co = idx % 32;
        int t  = (idx / 32) % 9;
        int ci = idx / (32 * 9);
        g_wr1[idx] = W1[((size_t)co * 2 + ci) * 9 + t];
        return;
    }
    idx -= 576;
    if (idx < 288 * 64)  { rp_tc(W2, (uint32_t*)g_wr2, 32, 64, idx);  return; }
    idx -= 288 * 64;
    if (idx < 576 * 128) { rp_tc(W3, (uint32_t*)g_wr3, 64, 128, idx); return; }
    idx -= 576 * 128;
    if (idx < 1152 * 256) rp_tc(W4, (uint32_t*)g_wr4, 128, 256, idx);
}

// ---------------- GAF kernel (NCHW out), coalesced row stores ----------------
__global__ void gaf_kernel(const float* __restrict__ x_raw)
{
    const int img = blockIdx.x;
    const int tid = threadIdx.x;   // 0..127
    __shared__ float xs[SS];
    __shared__ float ssq[SS];
    __shared__ float smn[4], smx[4];

    const float4 v4 = *(const float4*)(x_raw + (size_t)img * TT + tid * 4);
    float v = 0.25f * (v4.x + v4.y + v4.z + v4.w);

    float mn = v, mx = v;
    #pragma unroll
    for (int o = 16; o > 0; o >>= 1) {
        mn = fminf(mn, __shfl_xor_sync(0xffffffffu, mn, o));
        mx = fmaxf(mx, __shfl_xor_sync(0xffffffffu, mx, o));
    }
    const int warp = tid >> 5, lane = tid & 31;
    if (lane == 0) { smn[warp] = mn; smx[warp] = mx; }
    __syncthreads();
    mn = fminf(fminf(smn[0], smn[1]), fminf(smn[2], smn[3]));
    mx = fmaxf(fmaxf(smx[0], smx[1]), fmaxf(smx[2], smx[3]));

    float xn = 2.0f * (v - mn) / (mx - mn + 1e-8f) - 1.0f;
    xn = fminf(1.0f, fmaxf(-1.0f, xn));
    float sq = sqrtf(fminf(1.0f, fmaxf(0.0f, 1.0f - xn * xn)));
    xs[tid] = xn;
    ssq[tid] = sq;
    __syncthreads();

    const int c0 = lane * 4;
    float xj[4], sj[4];
    #pragma unroll
    for (int c = 0; c < 4; c++) { xj[c] = xs[c0 + c]; sj[c] = ssq[c0 + c]; }
    float* __restrict__ g0 = g_gaf + (size_t)img * (2 * SS * SS);
    float* __restrict__ g1 = g0 + SS * SS;
    for (int rb = 0; rb < SS; rb += 4) {
        const int row = rb + warp;
        const float xi = xs[row], si = ssq[row];
        float4 o0, o1;
        o0.x = xi * xj[0] - si * sj[0];  o1.x = si * xj[0] - xi * sj[0];
        o0.y = xi * xj[1] - si * sj[1];  o1.y = si * xj[1] - xi * sj[1];
        o0.z = xi * xj[2] - si * sj[2];  o1.z = si * xj[2] - xi * sj[2];
        o0.w = xi * xj[3] - si * sj[3];  o1.w = si * xj[3] - xi * sj[3];
        *(float4*)(g0 + row * SS + c0) = o0;
        *(float4*)(g1 + row * SS + c0) = o1;
    }
}

// ---------------- L1 direct conv (FFMA2), NCHW in -> NHWC out (tf32-rounded) --------
__global__ void __launch_bounds__(128)
conv1_ffma2(const float* __restrict__ in, const float* __restrict__ Wr,
            const float* __restrict__ bias, float* __restrict__ out)
{
    constexpr int CIN = 2, HIN = 128, COUT = 32, HOUT = 64, WQ = 16;
    const int tid  = threadIdx.x;
    const int sid  = tid + blockIdx.z * 128;
    const int n    = blockIdx.x;
    const int cout0 = blockIdx.y * 8;
    const int oh  = sid / WQ;
    const int ow0 = (sid % WQ) * 4;

    const float* __restrict__ inN = in + (size_t)n * CIN * HIN * HIN;

    unsigned long long acc[4][4];
    #pragma unroll
    for (int cp = 0; cp < 4; cp++)
        #pragma unroll
        for (int o = 0; o < 4; o++) acc[cp][o] = 0ull;

    const bool rguard = (ow0 * 2 + 8 < HIN);

    #pragma unroll
    for (int ci = 0; ci < CIN; ci++) {
        const float* __restrict__ wbase = Wr + ((size_t)ci * 9) * COUT + cout0;
        const float* __restrict__ inC = inN + (size_t)ci * HIN * HIN;
        #pragma unroll
        for (int kh = 0; kh < 3; kh++) {
            const int ih = oh * 2 + kh;
            if (ih >= HIN) break;
            const float* row = inC + (size_t)ih * HIN + ow0 * 2;
            float r[9];
            const float4 a = *(const float4*)row;
            const float4 b = *(const float4*)(row + 4);
            r[0]=a.x; r[1]=a.y; r[2]=a.z; r[3]=a.w;
            r[4]=b.x; r[5]=b.y; r[6]=b.z; r[7]=b.w;
            r[8] = rguard ? row[8] : 0.0f;
            unsigned long long pb[9];
            #pragma unroll
            for (int v = 0; v < 9; v++) pb[v] = pk2(r[v], r[v]);
            #pragma unroll
            for (int kw = 0; kw < 3; kw++) {
                const float* wp = wbase + (kh * 3 + kw) * COUT;
                const ulonglong2 wa = *(const ulonglong2*)(wp);
                const ulonglong2 wb = *(const ulonglong2*)(wp + 4);
                #pragma unroll
                for (int o = 0; o < 4; o++) {
                    const unsigned long long x = pb[2 * o + kw];
                    fma2(acc[0][o], wa.x, x);
                    fma2(acc[1][o], wa.y, x);
                    fma2(acc[2][o], wb.x, x);
                    fma2(acc[3][o], wb.y, x);
                }
            }
        }
    }

    float bv[8];
    #pragma unroll
    for (int c = 0; c < 8; c++) bv[c] = __ldg(bias + cout0 + c);
    #pragma unroll
    for (int o = 0; o < 4; o++) {
        float l0,h0,l1,h1,l2,h2,l3,h3;
        upk2(acc[0][o], l0, h0); upk2(acc[1][o], l1, h1);
        upk2(acc[2][o], l2, h2); upk2(acc[3][o], l3, h3);
        float4 vlo, vhi;   // tf32-round outputs so downstream MMA truncation is exact
        vlo.x = f2tf32f(fmaxf(l0 + bv[0], 0.f)); vlo.y = f2tf32f(fmaxf(h0 + bv[1], 0.f));
        vlo.z = f2tf32f(fmaxf(l1 + bv[2], 0.f)); vlo.w = f2tf32f(fmaxf(h1 + bv[3], 0.f));
        vhi.x = f2tf32f(fmaxf(l2 + bv[4], 0.f)); vhi.y = f2tf32f(fmaxf(h2 + bv[5], 0.f));
        vhi.z = f2tf32f(fmaxf(l3 + bv[6], 0.f)); vhi.w = f2tf32f(fmaxf(h3 + bv[7], 0.f));
        float* op = out + (((size_t)n * HOUT + oh) * HOUT + (ow0 + o)) * COUT + cout0;
        *(float4*)op = vlo;
        *(float4*)(op + 4) = vhi;
    }
}

// ---------------- tf32 mma.sync implicit-GEMM conv, 3-stage cp.async pipeline --------
// in: NHWC (tf32-rounded); Br: [k][COUT] tf32 bits; out: NHWC.
// CTA 256 thr, tile M=TM x N=COUT, K chunks of 32, 3-stage ring, 1 sync/chunk.
// Warp grid WM x WN (8 warps); warp tile (TM/WM) x (COUT/WN).
template<int CIN, int HIN, int COUT, int TM, int WM, int WN, bool CVTOUT>
__global__ void __launch_bounds__(256)
conv_mma(const float* __restrict__ in, const float* __restrict__ Br,
         const float* __restrict__ bias, float* __restrict__ out)
{
    static_assert(WM * WN == 8, "8 warps");
    constexpr int HOUT = HIN / 2;
    constexpr int P    = HOUT * HOUT;
    constexpr int K    = CIN * 9;
    constexpr int NCH  = K / 32;
    constexpr int CPT  = CIN / 32;
    constexpr int MF   = TM / (WM * 16);   // m fragments per warp
    constexpr int WNT  = COUT / WN;        // warp n-tile
    constexpr int NF   = WNT / 8;          // n fragments per warp
    constexpr int AST  = 36;               // A smem row stride (floats)
    constexpr int BST  = COUT + 8;         // B smem row stride (floats), ≡8 mod 32
    constexpr int AFL  = TM * AST;
    constexpr int BFL  = 32 * BST;
    constexpr int SFL  = AFL + BFL;        // floats per stage
    constexpr int TPR  = 256 / TM;         // threads per A row
    constexpr int CHK  = 8 / TPR;          // 16B chunks per thread (A row = CIN/4 16B)

    extern __shared__ float smf[];
    const uint32_t sm0 = smem_u32(smf);

    const int tid  = threadIdx.x;
    const int lane = tid & 31;
    const int wid  = tid >> 5;
    const int wm   = wid % WM;
    const int wn   = wid / WM;
    const int g    = lane >> 2;           // 0..7
    const int tq   = lane & 3;            // 0..3

    // A staging coords
    const int r    = tid / TPR;
    const int sub  = tid % TPR;
    const int pos  = blockIdx.x * TM + r;
    const int nimg = pos / P;
    const int rem  = pos % P;
    const int oh   = rem / HOUT, ow = rem % HOUT;

    const uint32_t a_dst_off = (uint32_t)(r * AST + sub * CHK * 4) * 4;

    auto prefetch = [&](int kc, int slot) {
        const uint32_t sbase = sm0 + (uint32_t)(slot * SFL) * 4;
        const int t   = kc / CPT;
        const int ci0 = (kc % CPT) * 32;
        const int kh = t / 3, kw = t % 3;
        const int ih = oh * 2 + kh, iw = ow * 2 + kw;
        const bool val = (ih < HIN) && (iw < HIN);
        const float* s = val
            ? in + ((((size_t)nimg * HIN + ih) * HIN + iw) * CIN + ci0) + sub * CHK * 4
            : in;
        const int sz = val ? 16 : 0;
        const uint32_t ad = sbase + a_dst_off;
        #pragma unroll
        for (int c = 0; c < CHK; c++)
            cpasync16(ad + c * 16, s + c * 4, sz);
        // B: 32 rows x COUT floats
        const float* bsrc = Br + (size_t)(kc * 32) * COUT;
        const uint32_t bd = sbase + (uint32_t)AFL * 4;
        #pragma unroll
        for (int j = 0; j < COUT / 32; j++) {
            const int cid = j * 256 + tid;
            const int k   = cid / (COUT / 4);
            const int cc  = cid % (COUT / 4);
            cpasync16(bd + (uint32_t)(k * BST + cc * 4) * 4, bsrc + (size_t)k * COUT + cc * 4, 16);
        }
    };

    prefetch(0, 0); CP_COMMIT();
    prefetch(1, 1); CP_COMMIT();

    float d[MF][NF][4];
    #pragma unroll
    for (int mf = 0; mf < MF; mf++)
        #pragma unroll
        for (int nf = 0; nf < NF; nf++)
            #pragma unroll
            for (int j = 0; j < 4; j++) d[mf][nf][j] = 0.f;

    int slot = 0;
    for (int c = 0; c < NCH; c++) {
        if (c + 1 < NCH) { CP_WAIT1(); } else { CP_WAIT0(); }
        __syncthreads();
        if (c + 2 < NCH) {
            int ps = slot + 2; if (ps >= 3) ps -= 3;
            prefetch(c + 2, ps);
            CP_COMMIT();
        }

        const uint32_t* A = (const uint32_t*)(smf + slot * SFL);
        const uint32_t* B = A + AFL;
        #pragma unroll
        for (int ks = 0; ks < 4; ks++) {
            uint32_t a[MF][4], b[NF][2];
            const int ac = ks * 8 + tq;
            #pragma unroll
            for (int mf = 0; mf < MF; mf++) {
                const int ar = wm * (16 * MF) + mf * 16 + g;
                a[mf][0] = A[ar * AST + ac];
                a[mf][1] = A[(ar + 8) * AST + ac];
                a[mf][2] = A[ar * AST + ac + 4];
                a[mf][3] = A[(ar + 8) * AST + ac + 4];
            }
            const int bkr = ks * 8 + tq;
            #pragma unroll
            for (int nf = 0; nf < NF; nf++) {
                const int bcc = wn * WNT + nf * 8 + g;
                b[nf][0] = B[bkr * BST + bcc];
                b[nf][1] = B[(bkr + 4) * BST + bcc];
            }
            #pragma unroll
            for (int mf = 0; mf < MF; mf++)
                #pragma unroll
                for (int nf = 0; nf < NF; nf++)
                    mma_tf32(d[mf][nf], a[mf], b[nf]);
        }
        if (++slot == 3) slot = 0;
    }

    // epilogue: bias + ReLU (+ optional tf32 round), NHWC float2 stores
    #pragma unroll
    for (int nf = 0; nf < NF; nf++) {
        const int col = wn * WNT + nf * 8 + 2 * tq;
        const float b0 = __ldg(bias + col);
        const float b1 = __ldg(bias + col + 1);
        #pragma unroll
        for (int mf = 0; mf < MF; mf++) {
            const int row0 = blockIdx.x * TM + wm * (16 * MF) + mf * 16 + g;
            float2 v0, v1;
            v0.x = fmaxf(d[mf][nf][0] + b0, 0.f);
            v0.y = fmaxf(d[mf][nf][1] + b1, 0.f);
            v1.x = fmaxf(d[mf][nf][2] + b0, 0.f);
            v1.y = fmaxf(d[mf][nf][3] + b1, 0.f);
            if (CVTOUT) {
                v0.x = f2tf32f(v0.x); v0.y = f2tf32f(v0.y);
                v1.x = f2tf32f(v1.x); v1.y = f2tf32f(v1.y);
            }
            *(float2*)(out + (size_t)row0 * COUT + col)       = v0;
            *(float2*)(out + (size_t)(row0 + 8) * COUT + col) = v1;
        }
    }
}

// ---------------- pool stage 1: per image, sum 64 positions ----------------
__global__ void pool1()
{
    const int img = blockIdx.x;
    const int k = threadIdx.x;  // 0..255
    const float* __restrict__ base = g_h4 + (size_t)img * 64 * 256 + k;
    float s = 0.0f;
    #pragma unroll
    for (int i = 0; i < 64; i++)
        s += base[(size_t)i * 256];
    g_pp[img * 256 + k] = s;
}
// ---------------- pool stage 2: sum over C=32 heads ----------------
__global__ void pool2()
{
    const int b = blockIdx.x;
    const int k = threadIdx.x;
    const float* __restrict__ p = g_pp + (size_t)b * 32 * 256 + k;
    float s = 0.0f;
    #pragma unroll
    for (int c = 0; c < 32; c++)
        s += p[(size_t)c * 256];
    g_pbar[b * 256 + k] = s * (1.0f / 2048.0f);
}

// ---------------- FC ----------------
__global__ void fc_kernel(const float* __restrict__ Wfc, const float* __restrict__ bfc,
                          float* __restrict__ out)
{
    const int b = blockIdx.x;
    const int l = threadIdx.x;
    float s = bfc[l];
    const float* p = g_pbar + b * 256;
    #pragma unroll 8
    for (int k = 0; k < 256; k++)
        s = fmaf(p[k], Wfc[k * LATENT + l], s);
    out[b * LATENT + l] = s;
}

// ---------------- launch ----------------
extern "C" void kernel_launch(void* const* d_in, const int* in_sizes, int n_in,
                              void* d_out, int out_size)
{
    const float* x_raw = (const float*)d_in[0];
    const float* W1 = (const float*)d_in[1];  const float* b1 = (const float*)d_in[2];
    const float* W2 = (const float*)d_in[3];  const float* b2 = (const float*)d_in[4];
    const float* W3 = (const float*)d_in[5];  const float* b3 = (const float*)d_in[6];
    const float* W4 = (const float*)d_in[7];  const float* b4 = (const float*)d_in[8];
    const float* Wfc = (const float*)d_in[9]; const float* bfc = (const float*)d_in[10];
    float* out = (float*)d_out;

    float *gaf, *h1, *h2, *h3, *h4, *wr1, *wr2, *wr3, *wr4;
    cudaGetSymbolAddress((void**)&gaf, g_gaf);
    cudaGetSymbolAddress((void**)&h1, g_h1);
    cudaGetSymbolAddress((void**)&h2, g_h2);
    cudaGetSymbolAddress((void**)&h3, g_h3);
    cudaGetSymbolAddress((void**)&h4, g_h4);
    cudaGetSymbolAddress((void**)&wr1, g_wr1);
    cudaGetSymbolAddress((void**)&wr2, g_wr2);
    cudaGetSymbolAddress((void**)&wr3, g_wr3);
    cudaGetSymbolAddress((void**)&wr4, g_wr4);

    // 3 stages of (A + B) floats
    const int smem2 = 3 * (256 * 36 + 32 * 72)  * 4;   // 138240
    const int smem3 = 3 * (128 * 36 + 32 * 136) * 4;   // 107520
    const int smem4 = 3 * (64  * 36 + 32 * 264) * 4;   // 129024
    cudaFuncSetAttribute((const void*)conv_mma<32, 64, 64, 256, 4, 2, true>,
                         cudaFuncAttributeMaxDynamicSharedMemorySize, smem2);
    cudaFuncSetAttribute((const void*)conv_mma<64, 32, 128, 128, 2, 4, true>,
                         cudaFuncAttributeMaxDynamicSharedMemorySize, smem3);
    cudaFuncSetAttribute((const void*)conv_mma<128, 16, 256, 64, 2, 4, false>,
                         cudaFuncAttributeMaxDynamicSharedMemorySize, smem4);

    const int rp_total = 576 + 288 * 64 + 576 * 128 + 1152 * 256;

    repack_all<<<(rp_total + 255) / 256, 256>>>(W1, W2, W3, W4);       // 0
    gaf_kernel<<<NIMG, 128>>>(x_raw);                                  // 1
    conv1_ffma2<<<dim3(NIMG, 4, 8), 128>>>(gaf, wr1, b1, h1);          // 2
    conv_mma<32, 64, 64, 256, 4, 2, true>  <<<NIMG * 1024 / 256, 256, smem2>>>(h1, wr2, b2, h2);  // 3
    conv_mma<64, 32, 128, 128, 2, 4, true> <<<NIMG * 256  / 128, 256, smem3>>>(h2, wr3, b3, h3);  // 4
    conv_mma<128, 16, 256, 64, 2, 4, false><<<NIMG * 64   / 64,  256, smem4>>>(h3, wr4, b4, h4);  // 5
    pool1<<<NIMG, 256>>>();                                            // 6
    pool2<<<BB, 256>>>();                                              // 7
    fc_kernel<<<BB, LATENT>>>(Wfc, bfc, out);                          // 8
}